// round 1
// baseline (speedup 1.0000x reference)
#include <cuda_runtime.h>
#include <math.h>
#include <math_constants.h>

#define NB   4
#define NPTS 8192
#define BN   (NB*NPTS)   // 32768
#define D    128
#define KNN  16

// ---------------- scratch (static device allocations) ----------------
__device__ float4 g_xyzw[BN];          // (-2x,-2y,-2z, |x|^2) per point
__device__ float  g_ksum[BN];          // feat . rowsum(Wk)
__device__ int    g_idx[BN*KNN];       // knn indices (within batch)
__device__ float  g_v[BN*D];           // feat @ Wv + bv
__device__ float  g_hbar[BN*D];        // sum_k attn_k * h_k
__device__ float  g_vbar[BN*D];        // sum_k attn_k * v_k
__device__ float  g_wkrs[D];           // rowsum over out-dim of Wk
__device__ float  g_wp2rs[D];          // rowsum over out-dim of Wp2
__device__ float  g_cvec[D];           // bp2 @ Wo + bo
__device__ float  g_wf[D*D];           // Wp2 @ Wo

// ---------------- tiny weight-prep kernels ----------------
__global__ void k_rowsums(const float* __restrict__ Wk, const float* __restrict__ Wp2) {
    int i = threadIdx.x;
    float a = 0.f, b = 0.f;
    for (int j = 0; j < D; ++j) { a += Wk[i*D + j]; b += Wp2[i*D + j]; }
    g_wkrs[i] = a; g_wp2rs[i] = b;
}

__global__ void k_cvec(const float* __restrict__ bp2, const float* __restrict__ Wo,
                       const float* __restrict__ bo) {
    int d = threadIdx.x;
    float a = bo[d];
    for (int k = 0; k < D; ++k) a = fmaf(bp2[k], Wo[k*D + d], a);
    g_cvec[d] = a;
}

__global__ void k_wfused(const float* __restrict__ Wp2, const float* __restrict__ Wo) {
    int d = threadIdx.x & (D-1);
    int i = blockIdx.x*2 + (threadIdx.x >> 7);
    float a = 0.f;
    for (int k = 0; k < D; ++k) a = fmaf(Wp2[i*D + k], Wo[k*D + d], a);
    g_wf[i*D + d] = a;
}

// ---------------- per-point prep: xyzw + ksum ----------------
__global__ void k_prep(const float* __restrict__ xyz, const float* __restrict__ feat) {
    int warp = threadIdx.x >> 5, lane = threadIdx.x & 31;
    int p = blockIdx.x*8 + warp;
    const float* fr = feat + (size_t)p*D;
    float acc = 0.f;
    #pragma unroll
    for (int i = 0; i < 4; ++i) {
        int d = lane + 32*i;
        acc = fmaf(fr[d], g_wkrs[d], acc);
    }
    #pragma unroll
    for (int off = 16; off; off >>= 1) acc += __shfl_xor_sync(0xffffffffu, acc, off);
    if (lane == 0) {
        g_ksum[p] = acc;
        float x = xyz[3*p], y = xyz[3*p+1], z = xyz[3*p+2];
        g_xyzw[p] = make_float4(-2.f*x, -2.f*y, -2.f*z, x*x + y*y + z*z);
    }
}

// ---------------- brute-force kNN (thread per query) ----------------
#define TPC 2048
__global__ void k_topk(const float* __restrict__ xyz) {
    __shared__ float4 tile[TPC];
    int b  = blockIdx.y;
    int q  = blockIdx.x*128 + threadIdx.x;
    int qg = b*NPTS + q;
    float qx = xyz[3*qg], qy = xyz[3*qg+1], qz = xyz[3*qg+2];

    float dist[KNN]; int nid[KNN];
    #pragma unroll
    for (int t = 0; t < KNN; ++t) { dist[t] = CUDART_INF_F; nid[t] = 0; }

    const float4* cand = g_xyzw + b*NPTS;
    for (int c0 = 0; c0 < NPTS; c0 += TPC) {
        __syncthreads();
        #pragma unroll
        for (int i = 0; i < TPC/128; ++i)
            tile[threadIdx.x + i*128] = cand[c0 + threadIdx.x + i*128];
        __syncthreads();

        float thresh = dist[KNN-1];
        #pragma unroll 4
        for (int t = 0; t < TPC; ++t) {
            float4 c = tile[t];
            // key = |c|^2 - 2*q.c  (== dist - |q|^2, ordering-equivalent)
            float key = fmaf(c.x, qx, fmaf(c.y, qy, fmaf(c.z, qz, c.w)));
            if (key < thresh) {                 // strict: keep earlier index on ties
                float ck = key; int ci = c0 + t;
                #pragma unroll
                for (int s = 0; s < KNN; ++s) { // branchless bubble insert
                    if (ck <= dist[s]) {
                        float td = dist[s]; int ti = nid[s];
                        dist[s] = ck; nid[s] = ci;
                        ck = td; ci = ti;
                    }
                }
                thresh = dist[KNN-1];
            }
        }
    }
    int* op = g_idx + (size_t)qg*KNN;
    #pragma unroll
    for (int t = 0; t < KNN; ++t) op[t] = nid[t];
}

// ---------------- v = feat @ Wv + bv ----------------
__global__ void k_gemm_v(const float* __restrict__ feat, const float* __restrict__ Wv,
                         const float* __restrict__ bv) {
    __shared__ float As[16][132];
    __shared__ float Ws[16][132];
    int m0 = blockIdx.x*128;
    int tx = threadIdx.x & 15, ty = threadIdx.x >> 4;
    float acc[8][8];
    #pragma unroll
    for (int i = 0; i < 8; ++i)
        #pragma unroll
        for (int j = 0; j < 8; ++j) acc[i][j] = 0.f;

    for (int kc = 0; kc < D; kc += 16) {
        __syncthreads();
        { // A chunk transposed into As[k][m]
            int c = threadIdx.x & 3, r = threadIdx.x >> 2;
            #pragma unroll
            for (int rr = 0; rr < 2; ++rr) {
                int mm = r + rr*64;
                float4 v = *(const float4*)&feat[(size_t)(m0+mm)*D + kc + c*4];
                As[c*4+0][mm] = v.x; As[c*4+1][mm] = v.y;
                As[c*4+2][mm] = v.z; As[c*4+3][mm] = v.w;
            }
        }
        { // W chunk
            int k = threadIdx.x >> 5, c4 = threadIdx.x & 31;
            #pragma unroll
            for (int kk = 0; kk < 2; ++kk) {
                float4 v = *(const float4*)&Wv[(size_t)(kc + k + kk*8)*D + c4*4];
                Ws[k + kk*8][c4*4+0] = v.x; Ws[k + kk*8][c4*4+1] = v.y;
                Ws[k + kk*8][c4*4+2] = v.z; Ws[k + kk*8][c4*4+3] = v.w;
            }
        }
        __syncthreads();
        #pragma unroll
        for (int k = 0; k < 16; ++k) {
            float a[8], bb[8];
            #pragma unroll
            for (int i = 0; i < 8; ++i) a[i]  = As[k][ty*8 + i];
            #pragma unroll
            for (int j = 0; j < 8; ++j) bb[j] = Ws[k][tx*8 + j];
            #pragma unroll
            for (int i = 0; i < 8; ++i)
                #pragma unroll
                for (int j = 0; j < 8; ++j) acc[i][j] = fmaf(a[i], bb[j], acc[i][j]);
        }
    }
    #pragma unroll
    for (int i = 0; i < 8; ++i) {
        int m = m0 + ty*8 + i;
        #pragma unroll
        for (int j = 0; j < 8; ++j) acc[i][j] += bv[tx*8 + j];
        *(float4*)&g_v[(size_t)m*D + tx*8]     = make_float4(acc[i][0], acc[i][1], acc[i][2], acc[i][3]);
        *(float4*)&g_v[(size_t)m*D + tx*8 + 4] = make_float4(acc[i][4], acc[i][5], acc[i][6], acc[i][7]);
    }
}

// ---------------- fused attention (warp per point) ----------------
__global__ void k_fuse(const float* __restrict__ xyz, const float* __restrict__ Wp1,
                       const float* __restrict__ bp1) {
    __shared__ float sw0[D], sw1[D], sw2[D], sb1[D], srs[D];
    int tid = threadIdx.x;
    sw0[tid] = Wp1[tid]; sw1[tid] = Wp1[D + tid]; sw2[tid] = Wp1[2*D + tid];
    sb1[tid] = bp1[tid]; srs[tid] = g_wp2rs[tid];
    __syncthreads();

    int warp = tid >> 5, lane = tid & 31;
    int p = blockIdx.x*4 + warp;
    int bbase = p & ~(NPTS-1);   // b*NPTS

    float w0[4], w1[4], w2[4], b1r[4], rs[4];
    #pragma unroll
    for (int i = 0; i < 4; ++i) {
        int d = lane + 32*i;
        w0[i] = sw0[d]; w1[i] = sw1[d]; w2[i] = sw2[d]; b1r[i] = sb1[d]; rs[i] = srs[d];
    }

    float rx = 0.f, ry = 0.f, rz = 0.f, ks = 0.f; int row = 0;
    if (lane < KNN) {
        int nb = g_idx[(size_t)p*KNN + lane];
        row = bbase + nb;
        float qx = xyz[3*p], qy = xyz[3*p+1], qz = xyz[3*p+2];
        rx = qx - xyz[3*row]; ry = qy - xyz[3*row+1]; rz = qz - xyz[3*row+2];
        ks = g_ksum[row];
    }

    // pass 1: attention logits  score_k = h_k . rowsum(Wp2) - ksum_k
    float mysc = -CUDART_INF_F;
    #pragma unroll
    for (int k = 0; k < KNN; ++k) {
        float bx = __shfl_sync(0xffffffffu, rx, k);
        float by = __shfl_sync(0xffffffffu, ry, k);
        float bz = __shfl_sync(0xffffffffu, rz, k);
        float part = 0.f;
        #pragma unroll
        for (int i = 0; i < 4; ++i) {
            float h = fmaf(bx, w0[i], fmaf(by, w1[i], fmaf(bz, w2[i], b1r[i])));
            h = fmaxf(h, 0.f);
            part = fmaf(h, rs[i], part);
        }
        #pragma unroll
        for (int off = 16; off; off >>= 1) part += __shfl_xor_sync(0xffffffffu, part, off);
        if (lane == k) mysc = part - ks;
    }
    // softmax over the 16 neighbor lanes
    float mx = mysc;
    #pragma unroll
    for (int off = 16; off; off >>= 1) mx = fmaxf(mx, __shfl_xor_sync(0xffffffffu, mx, off));
    float e = (lane < KNN) ? __expf(mysc - mx) : 0.f;
    float ssum = e;
    #pragma unroll
    for (int off = 16; off; off >>= 1) ssum += __shfl_xor_sync(0xffffffffu, ssum, off);
    float attn = e / ssum;

    // pass 2: hbar = sum attn*h, vbar = sum attn*v
    float hb[4] = {0,0,0,0}, vb[4] = {0,0,0,0};
    #pragma unroll
    for (int k = 0; k < KNN; ++k) {
        float a  = __shfl_sync(0xffffffffu, attn, k);
        float bx = __shfl_sync(0xffffffffu, rx, k);
        float by = __shfl_sync(0xffffffffu, ry, k);
        float bz = __shfl_sync(0xffffffffu, rz, k);
        int   r  = __shfl_sync(0xffffffffu, row, k);
        const float* vr = g_v + (size_t)r*D;
        #pragma unroll
        for (int i = 0; i < 4; ++i) {
            int d = lane + 32*i;
            float h = fmaf(bx, w0[i], fmaf(by, w1[i], fmaf(bz, w2[i], b1r[i])));
            h = fmaxf(h, 0.f);
            hb[i] = fmaf(a, h, hb[i]);
            vb[i] = fmaf(a, vr[d], vb[i]);
        }
    }
    #pragma unroll
    for (int i = 0; i < 4; ++i) {
        int d = lane + 32*i;
        g_hbar[(size_t)p*D + d] = hb[i];
        g_vbar[(size_t)p*D + d] = vb[i];
    }
}

// ---------------- out = feat + gamma*(vbar@Wo + hbar@Wf + cvec) ----------------
__global__ void k_out(const float* __restrict__ feat, const float* __restrict__ Wo,
                      const float* __restrict__ gamma, float* __restrict__ out) {
    __shared__ float As[16][132];
    __shared__ float Ws[16][132];
    int m0 = blockIdx.x*128;
    int tx = threadIdx.x & 15, ty = threadIdx.x >> 4;
    float acc[8][8];
    #pragma unroll
    for (int i = 0; i < 8; ++i)
        #pragma unroll
        for (int j = 0; j < 8; ++j) acc[i][j] = 0.f;

    for (int ph = 0; ph < 2; ++ph) {
        const float* A = ph ? g_hbar : g_vbar;
        const float* W = ph ? g_wf   : Wo;
        for (int kc = 0; kc < D; kc += 16) {
            __syncthreads();
            { int c = threadIdx.x & 3, r = threadIdx.x >> 2;
              #pragma unroll
              for (int rr = 0; rr < 2; ++rr) {
                  int mm = r + rr*64;
                  float4 v = *(const float4*)&A[(size_t)(m0+mm)*D + kc + c*4];
                  As[c*4+0][mm] = v.x; As[c*4+1][mm] = v.y;
                  As[c*4+2][mm] = v.z; As[c*4+3][mm] = v.w;
              }
            }
            { int k = threadIdx.x >> 5, c4 = threadIdx.x & 31;
              #pragma unroll
              for (int kk = 0; kk < 2; ++kk) {
                  float4 v = *(const float4*)&W[(size_t)(kc + k + kk*8)*D + c4*4];
                  Ws[k + kk*8][c4*4+0] = v.x; Ws[k + kk*8][c4*4+1] = v.y;
                  Ws[k + kk*8][c4*4+2] = v.z; Ws[k + kk*8][c4*4+3] = v.w;
              }
            }
            __syncthreads();
            #pragma unroll
            for (int k = 0; k < 16; ++k) {
                float a[8], bb[8];
                #pragma unroll
                for (int i = 0; i < 8; ++i) a[i]  = As[k][ty*8 + i];
                #pragma unroll
                for (int j = 0; j < 8; ++j) bb[j] = Ws[k][tx*8 + j];
                #pragma unroll
                for (int i = 0; i < 8; ++i)
                    #pragma unroll
                    for (int j = 0; j < 8; ++j) acc[i][j] = fmaf(a[i], bb[j], acc[i][j]);
            }
        }
    }
    float g = *gamma;
    float cv[8];
    #pragma unroll
    for (int j = 0; j < 8; ++j) cv[j] = g_cvec[tx*8 + j];
    #pragma unroll
    for (int i = 0; i < 8; ++i) {
        int m = m0 + ty*8 + i;
        float4 f0 = *(const float4*)&feat[(size_t)m*D + tx*8];
        float4 f1 = *(const float4*)&feat[(size_t)m*D + tx*8 + 4];
        float o0 = f0.x + g*(acc[i][0] + cv[0]);
        float o1 = f0.y + g*(acc[i][1] + cv[1]);
        float o2 = f0.z + g*(acc[i][2] + cv[2]);
        float o3 = f0.w + g*(acc[i][3] + cv[3]);
        float o4 = f1.x + g*(acc[i][4] + cv[4]);
        float o5 = f1.y + g*(acc[i][5] + cv[5]);
        float o6 = f1.z + g*(acc[i][6] + cv[6]);
        float o7 = f1.w + g*(acc[i][7] + cv[7]);
        *(float4*)&out[(size_t)m*D + tx*8]     = make_float4(o0, o1, o2, o3);
        *(float4*)&out[(size_t)m*D + tx*8 + 4] = make_float4(o4, o5, o6, o7);
    }
}

// ---------------- launch ----------------
extern "C" void kernel_launch(void* const* d_in, const int* in_sizes, int n_in,
                              void* d_out, int out_size) {
    const float* xyz  = (const float*)d_in[0];
    const float* feat = (const float*)d_in[1];
    // d_in[2]=Wq, d_in[3]=bq : mathematically cancel in softmax, unused
    const float* Wk   = (const float*)d_in[4];
    // d_in[5]=bk : cancels
    const float* Wv   = (const float*)d_in[6];
    const float* bv   = (const float*)d_in[7];
    const float* Wp1  = (const float*)d_in[8];
    const float* bp1  = (const float*)d_in[9];
    const float* Wp2  = (const float*)d_in[10];
    const float* bp2  = (const float*)d_in[11];
    const float* Wo   = (const float*)d_in[12];
    const float* bo   = (const float*)d_in[13];
    const float* gmm  = (const float*)d_in[14];
    float* out = (float*)d_out;

    k_rowsums<<<1, 128>>>(Wk, Wp2);
    k_cvec<<<1, 128>>>(bp2, Wo, bo);
    k_wfused<<<64, 256>>>(Wp2, Wo);
    k_prep<<<BN/8, 256>>>(xyz, feat);
    k_topk<<<dim3(NPTS/128, NB), 128>>>(xyz);
    k_gemm_v<<<BN/128, 256>>>(feat, Wv, bv);
    k_fuse<<<BN/4, 128>>>(xyz, Wp1, bp1);
    k_out<<<BN/128, 256>>>(feat, Wo, gmm, out);
}

// round 2
// speedup vs baseline: 1.3945x; 1.3945x over previous
#include <cuda_runtime.h>
#include <math.h>
#include <math_constants.h>

#define NB   4
#define NPTS 8192
#define BN   (NB*NPTS)   // 32768
#define D    128
#define KNN  16

// ---------------- scratch (static device allocations) ----------------
__device__ float4 g_xyzw[BN];          // (-2x,-2y,-2z, |x|^2) per point
__device__ float  g_ksum[BN];          // feat . rowsum(Wk)
__device__ int    g_idx[BN*KNN];       // knn indices (within batch)
__device__ float  g_v[BN*D];           // feat @ Wv + bv
__device__ float  g_hbar[BN*D];        // sum_k attn_k * h_k
__device__ float  g_vbar[BN*D];        // sum_k attn_k * v_k
__device__ float  g_wkrs[D];           // rowsum over out-dim of Wk
__device__ float  g_wp2rs[D];          // rowsum over out-dim of Wp2
__device__ float  g_cvec[D];           // bp2 @ Wo + bo
__device__ float  g_wf[D*D];           // Wp2 @ Wo

// ---------------- weight prep (merged) ----------------
__global__ void k_weights(const float* __restrict__ Wk, const float* __restrict__ Wp2,
                          const float* __restrict__ bp2, const float* __restrict__ Wo,
                          const float* __restrict__ bo) {
    int i = threadIdx.x;
    float a = 0.f, b = 0.f, c = bo[i];
    for (int j = 0; j < D; ++j) { a += Wk[i*D + j]; b += Wp2[i*D + j]; }
    for (int k = 0; k < D; ++k) c = fmaf(bp2[k], Wo[k*D + i], c);
    g_wkrs[i] = a; g_wp2rs[i] = b; g_cvec[i] = c;
}

__global__ void k_wfused(const float* __restrict__ Wp2, const float* __restrict__ Wo) {
    int d = threadIdx.x & (D-1);
    int i = blockIdx.x*2 + (threadIdx.x >> 7);
    float a = 0.f;
    for (int k = 0; k < D; ++k) a = fmaf(Wp2[i*D + k], Wo[k*D + d], a);
    g_wf[i*D + d] = a;
}

// ---------------- per-point prep: xyzw + ksum ----------------
__global__ void k_prep(const float* __restrict__ xyz, const float* __restrict__ feat) {
    int warp = threadIdx.x >> 5, lane = threadIdx.x & 31;
    int p = blockIdx.x*8 + warp;
    const float* fr = feat + (size_t)p*D;
    float acc = 0.f;
    #pragma unroll
    for (int i = 0; i < 4; ++i) {
        int d = lane + 32*i;
        acc = fmaf(fr[d], g_wkrs[d], acc);
    }
    #pragma unroll
    for (int off = 16; off; off >>= 1) acc += __shfl_xor_sync(0xffffffffu, acc, off);
    if (lane == 0) {
        g_ksum[p] = acc;
        float x = xyz[3*p], y = xyz[3*p+1], z = xyz[3*p+2];
        g_xyzw[p] = make_float4(-2.f*x, -2.f*y, -2.f*z, x*x + y*y + z*z);
    }
}

// ---------------- brute-force kNN: thread/query, deferred batched inserts ----------------
#define TPC 1024
__global__ void __launch_bounds__(32) k_topk(const float* __restrict__ xyz) {
    __shared__ float4 tile[TPC];
    int b  = blockIdx.y;
    int q  = blockIdx.x*32 + threadIdx.x;
    int qg = b*NPTS + q;
    float qx = xyz[3*qg], qy = xyz[3*qg+1], qz = xyz[3*qg+2];

    float dist[KNN]; int nid[KNN];
    #pragma unroll
    for (int t = 0; t < KNN; ++t) { dist[t] = CUDART_INF_F; nid[t] = 0; }

    float thresh = CUDART_INF_F;
    float pkey = 0.f; int pidx = 0; bool pval = false;

    const float4* cand = g_xyzw + b*NPTS;
    for (int c0 = 0; c0 < NPTS; c0 += TPC) {
        __syncwarp();
        #pragma unroll
        for (int i = 0; i < TPC/32; ++i)
            tile[threadIdx.x + i*32] = cand[c0 + threadIdx.x + i*32];
        __syncwarp();

        #pragma unroll 4
        for (int t = 0; t < TPC; ++t) {
            float4 c = tile[t];
            // key = |c|^2 - 2*q.c  (== dist - |q|^2, ordering-equivalent)
            float key = fmaf(c.x, qx, fmaf(c.y, qy, fmaf(c.z, qz, c.w)));
            bool hit = key < thresh;
            bool conflict = hit && pval;
            if (__any_sync(0xffffffffu, conflict)) {
                // warp-uniform flush: every lane with a pending entry inserts now
                if (pval) {
                    float ck = pkey; int ci = pidx;
                    #pragma unroll
                    for (int s = 0; s < KNN; ++s) {
                        bool sw = (ck <= dist[s]);
                        float td = dist[s]; int ti = nid[s];
                        dist[s] = sw ? ck : td;  nid[s] = sw ? ci : ti;
                        ck = sw ? td : ck;       ci = sw ? ti : ci;
                    }
                    thresh = dist[KNN-1];
                }
                pval = false;
            }
            if (hit) { pkey = key; pidx = c0 + t; pval = true; }
        }
    }
    // final flush
    if (pval) {
        float ck = pkey; int ci = pidx;
        #pragma unroll
        for (int s = 0; s < KNN; ++s) {
            bool sw = (ck <= dist[s]);
            float td = dist[s]; int ti = nid[s];
            dist[s] = sw ? ck : td;  nid[s] = sw ? ci : ti;
            ck = sw ? td : ck;       ci = sw ? ti : ci;
        }
    }
    int* op = g_idx + (size_t)qg*KNN;
    #pragma unroll
    for (int t = 0; t < KNN; ++t) op[t] = nid[t];
}

// ---------------- v = feat @ Wv + bv ----------------
__global__ void k_gemm_v(const float* __restrict__ feat, const float* __restrict__ Wv,
                         const float* __restrict__ bv) {
    __shared__ float As[16][132];
    __shared__ float Ws[16][132];
    int m0 = blockIdx.x*128;
    int tx = threadIdx.x & 15, ty = threadIdx.x >> 4;
    float acc[8][8];
    #pragma unroll
    for (int i = 0; i < 8; ++i)
        #pragma unroll
        for (int j = 0; j < 8; ++j) acc[i][j] = 0.f;

    for (int kc = 0; kc < D; kc += 16) {
        __syncthreads();
        { // A chunk transposed into As[k][m]
            int c = threadIdx.x & 3, r = threadIdx.x >> 2;
            #pragma unroll
            for (int rr = 0; rr < 2; ++rr) {
                int mm = r + rr*64;
                float4 v = *(const float4*)&feat[(size_t)(m0+mm)*D + kc + c*4];
                As[c*4+0][mm] = v.x; As[c*4+1][mm] = v.y;
                As[c*4+2][mm] = v.z; As[c*4+3][mm] = v.w;
            }
        }
        { // W chunk
            int k = threadIdx.x >> 5, c4 = threadIdx.x & 31;
            #pragma unroll
            for (int kk = 0; kk < 2; ++kk) {
                float4 v = *(const float4*)&Wv[(size_t)(kc + k + kk*8)*D + c4*4];
                Ws[k + kk*8][c4*4+0] = v.x; Ws[k + kk*8][c4*4+1] = v.y;
                Ws[k + kk*8][c4*4+2] = v.z; Ws[k + kk*8][c4*4+3] = v.w;
            }
        }
        __syncthreads();
        #pragma unroll
        for (int k = 0; k < 16; ++k) {
            float a[8], bb[8];
            #pragma unroll
            for (int i = 0; i < 8; ++i) a[i]  = As[k][ty*8 + i];
            #pragma unroll
            for (int j = 0; j < 8; ++j) bb[j] = Ws[k][tx*8 + j];
            #pragma unroll
            for (int i = 0; i < 8; ++i)
                #pragma unroll
                for (int j = 0; j < 8; ++j) acc[i][j] = fmaf(a[i], bb[j], acc[i][j]);
        }
    }
    #pragma unroll
    for (int i = 0; i < 8; ++i) {
        int m = m0 + ty*8 + i;
        #pragma unroll
        for (int j = 0; j < 8; ++j) acc[i][j] += bv[tx*8 + j];
        *(float4*)&g_v[(size_t)m*D + tx*8]     = make_float4(acc[i][0], acc[i][1], acc[i][2], acc[i][3]);
        *(float4*)&g_v[(size_t)m*D + tx*8 + 4] = make_float4(acc[i][4], acc[i][5], acc[i][6], acc[i][7]);
    }
}

// ---------------- fused attention (warp per point) ----------------
__global__ void k_fuse(const float* __restrict__ xyz, const float* __restrict__ Wp1,
                       const float* __restrict__ bp1) {
    __shared__ float sw0[D], sw1[D], sw2[D], sb1[D], srs[D];
    int tid = threadIdx.x;
    sw0[tid] = Wp1[tid]; sw1[tid] = Wp1[D + tid]; sw2[tid] = Wp1[2*D + tid];
    sb1[tid] = bp1[tid]; srs[tid] = g_wp2rs[tid];
    __syncthreads();

    int warp = tid >> 5, lane = tid & 31;
    int p = blockIdx.x*4 + warp;
    int bbase = p & ~(NPTS-1);   // b*NPTS

    float w0[4], w1[4], w2[4], b1r[4], rs[4];
    #pragma unroll
    for (int i = 0; i < 4; ++i) {
        int d = lane + 32*i;
        w0[i] = sw0[d]; w1[i] = sw1[d]; w2[i] = sw2[d]; b1r[i] = sb1[d]; rs[i] = srs[d];
    }

    float rx = 0.f, ry = 0.f, rz = 0.f, ks = 0.f; int row = 0;
    if (lane < KNN) {
        int nb = g_idx[(size_t)p*KNN + lane];
        row = bbase + nb;
        float qx = xyz[3*p], qy = xyz[3*p+1], qz = xyz[3*p+2];
        rx = qx - xyz[3*row]; ry = qy - xyz[3*row+1]; rz = qz - xyz[3*row+2];
        ks = g_ksum[row];
    }

    // pass 1: attention logits  score_k = h_k . rowsum(Wp2) - ksum_k
    float mysc = -CUDART_INF_F;
    #pragma unroll
    for (int k = 0; k < KNN; ++k) {
        float bx = __shfl_sync(0xffffffffu, rx, k);
        float by = __shfl_sync(0xffffffffu, ry, k);
        float bz = __shfl_sync(0xffffffffu, rz, k);
        float part = 0.f;
        #pragma unroll
        for (int i = 0; i < 4; ++i) {
            float h = fmaf(bx, w0[i], fmaf(by, w1[i], fmaf(bz, w2[i], b1r[i])));
            h = fmaxf(h, 0.f);
            part = fmaf(h, rs[i], part);
        }
        #pragma unroll
        for (int off = 16; off; off >>= 1) part += __shfl_xor_sync(0xffffffffu, part, off);
        if (lane == k) mysc = part - ks;
    }
    // softmax over the 16 neighbor lanes
    float mx = mysc;
    #pragma unroll
    for (int off = 16; off; off >>= 1) mx = fmaxf(mx, __shfl_xor_sync(0xffffffffu, mx, off));
    float e = (lane < KNN) ? __expf(mysc - mx) : 0.f;
    float ssum = e;
    #pragma unroll
    for (int off = 16; off; off >>= 1) ssum += __shfl_xor_sync(0xffffffffu, ssum, off);
    float attn = e / ssum;

    // pass 2: hbar = sum attn*h, vbar = sum attn*v
    float hb[4] = {0,0,0,0}, vb[4] = {0,0,0,0};
    #pragma unroll
    for (int k = 0; k < KNN; ++k) {
        float a  = __shfl_sync(0xffffffffu, attn, k);
        float bx = __shfl_sync(0xffffffffu, rx, k);
        float by = __shfl_sync(0xffffffffu, ry, k);
        float bz = __shfl_sync(0xffffffffu, rz, k);
        int   r  = __shfl_sync(0xffffffffu, row, k);
        const float* vr = g_v + (size_t)r*D;
        #pragma unroll
        for (int i = 0; i < 4; ++i) {
            int d = lane + 32*i;
            float h = fmaf(bx, w0[i], fmaf(by, w1[i], fmaf(bz, w2[i], b1r[i])));
            h = fmaxf(h, 0.f);
            hb[i] = fmaf(a, h, hb[i]);
            vb[i] = fmaf(a, vr[d], vb[i]);
        }
    }
    #pragma unroll
    for (int i = 0; i < 4; ++i) {
        int d = lane + 32*i;
        g_hbar[(size_t)p*D + d] = hb[i];
        g_vbar[(size_t)p*D + d] = vb[i];
    }
}

// ---------------- out = feat + gamma*(vbar@Wo + hbar@Wf + cvec) ----------------
__global__ void k_out(const float* __restrict__ feat, const float* __restrict__ Wo,
                      const float* __restrict__ gamma, float* __restrict__ out) {
    __shared__ float As[16][132];
    __shared__ float Ws[16][132];
    int m0 = blockIdx.x*128;
    int tx = threadIdx.x & 15, ty = threadIdx.x >> 4;
    float acc[8][8];
    #pragma unroll
    for (int i = 0; i < 8; ++i)
        #pragma unroll
        for (int j = 0; j < 8; ++j) acc[i][j] = 0.f;

    for (int ph = 0; ph < 2; ++ph) {
        const float* A = ph ? g_hbar : g_vbar;
        const float* W = ph ? g_wf   : Wo;
        for (int kc = 0; kc < D; kc += 16) {
            __syncthreads();
            { int c = threadIdx.x & 3, r = threadIdx.x >> 2;
              #pragma unroll
              for (int rr = 0; rr < 2; ++rr) {
                  int mm = r + rr*64;
                  float4 v = *(const float4*)&A[(size_t)(m0+mm)*D + kc + c*4];
                  As[c*4+0][mm] = v.x; As[c*4+1][mm] = v.y;
                  As[c*4+2][mm] = v.z; As[c*4+3][mm] = v.w;
              }
            }
            { int k = threadIdx.x >> 5, c4 = threadIdx.x & 31;
              #pragma unroll
              for (int kk = 0; kk < 2; ++kk) {
                  float4 v = *(const float4*)&W[(size_t)(kc + k + kk*8)*D + c4*4];
                  Ws[k + kk*8][c4*4+0] = v.x; Ws[k + kk*8][c4*4+1] = v.y;
                  Ws[k + kk*8][c4*4+2] = v.z; Ws[k + kk*8][c4*4+3] = v.w;
              }
            }
            __syncthreads();
            #pragma unroll
            for (int k = 0; k < 16; ++k) {
                float a[8], bb[8];
                #pragma unroll
                for (int i = 0; i < 8; ++i) a[i]  = As[k][ty*8 + i];
                #pragma unroll
                for (int j = 0; j < 8; ++j) bb[j] = Ws[k][tx*8 + j];
                #pragma unroll
                for (int i = 0; i < 8; ++i)
                    #pragma unroll
                    for (int j = 0; j < 8; ++j) acc[i][j] = fmaf(a[i], bb[j], acc[i][j]);
            }
        }
    }
    float g = *gamma;
    float cv[8];
    #pragma unroll
    for (int j = 0; j < 8; ++j) cv[j] = g_cvec[tx*8 + j];
    #pragma unroll
    for (int i = 0; i < 8; ++i) {
        int m = m0 + ty*8 + i;
        float4 f0 = *(const float4*)&feat[(size_t)m*D + tx*8];
        float4 f1 = *(const float4*)&feat[(size_t)m*D + tx*8 + 4];
        float o0 = f0.x + g*(acc[i][0] + cv[0]);
        float o1 = f0.y + g*(acc[i][1] + cv[1]);
        float o2 = f0.z + g*(acc[i][2] + cv[2]);
        float o3 = f0.w + g*(acc[i][3] + cv[3]);
        float o4 = f1.x + g*(acc[i][4] + cv[4]);
        float o5 = f1.y + g*(acc[i][5] + cv[5]);
        float o6 = f1.z + g*(acc[i][6] + cv[6]);
        float o7 = f1.w + g*(acc[i][7] + cv[7]);
        *(float4*)&out[(size_t)m*D + tx*8]     = make_float4(o0, o1, o2, o3);
        *(float4*)&out[(size_t)m*D + tx*8 + 4] = make_float4(o4, o5, o6, o7);
    }
}

// ---------------- launch ----------------
extern "C" void kernel_launch(void* const* d_in, const int* in_sizes, int n_in,
                              void* d_out, int out_size) {
    const float* xyz  = (const float*)d_in[0];
    const float* feat = (const float*)d_in[1];
    // d_in[2]=Wq, d_in[3]=bq, d_in[5]=bk : mathematically cancel in softmax, unused
    const float* Wk   = (const float*)d_in[4];
    const float* Wv   = (const float*)d_in[6];
    const float* bv   = (const float*)d_in[7];
    const float* Wp1  = (const float*)d_in[8];
    const float* bp1  = (const float*)d_in[9];
    const float* Wp2  = (const float*)d_in[10];
    const float* bp2  = (const float*)d_in[11];
    const float* Wo   = (const float*)d_in[12];
    const float* bo   = (const float*)d_in[13];
    const float* gmm  = (const float*)d_in[14];
    float* out = (float*)d_out;

    k_weights<<<1, 128>>>(Wk, Wp2, bp2, Wo, bo);
    k_wfused<<<64, 256>>>(Wp2, Wo);
    k_prep<<<BN/8, 256>>>(xyz, feat);
    k_topk<<<dim3(NPTS/32, NB), 32>>>(xyz);          // launch #4 -> ncu capture slot
    k_gemm_v<<<BN/128, 256>>>(feat, Wv, bv);
    k_fuse<<<BN/4, 128>>>(xyz, Wp1, bp1);
    k_out<<<BN/128, 256>>>(feat, Wo, gmm, out);
}

// round 3
// speedup vs baseline: 1.4727x; 1.0561x over previous
#include <cuda_runtime.h>
#include <math.h>
#include <math_constants.h>

#define NB   4
#define NPTS 8192
#define BN   (NB*NPTS)   // 32768
#define D    128
#define KNN  16

// ---------------- scratch (static device allocations) ----------------
__device__ float4 g_xyzw[BN];          // (-2x,-2y,-2z, |x|^2) per point
__device__ float  g_ksum[BN];          // feat . rowsum(Wk)
__device__ int    g_idx[BN*KNN];       // knn indices (within batch)
__device__ float  g_v[BN*D];           // feat @ Wv + bv
__device__ float  g_hbar[BN*D];        // sum_k attn_k * h_k
__device__ float  g_vbar[BN*D];        // sum_k attn_k * v_k
__device__ float  g_wkrs[D];           // rowsum over out-dim of Wk
__device__ float  g_wp2rs[D];          // rowsum over out-dim of Wp2
__device__ float  g_cvec[D];           // bp2 @ Wo + bo
__device__ float  g_wf[D*D];           // Wp2 @ Wo

// ---------------- weight prep (merged) ----------------
__global__ void k_weights(const float* __restrict__ Wk, const float* __restrict__ Wp2,
                          const float* __restrict__ bp2, const float* __restrict__ Wo,
                          const float* __restrict__ bo) {
    int i = threadIdx.x;
    float a = 0.f, b = 0.f, c = bo[i];
    for (int j = 0; j < D; ++j) { a += Wk[i*D + j]; b += Wp2[i*D + j]; }
    for (int k = 0; k < D; ++k) c = fmaf(bp2[k], Wo[k*D + i], c);
    g_wkrs[i] = a; g_wp2rs[i] = b; g_cvec[i] = c;
}

__global__ void k_wfused(const float* __restrict__ Wp2, const float* __restrict__ Wo) {
    int d = threadIdx.x & (D-1);
    int i = blockIdx.x*2 + (threadIdx.x >> 7);
    float a = 0.f;
    for (int k = 0; k < D; ++k) a = fmaf(Wp2[i*D + k], Wo[k*D + d], a);
    g_wf[i*D + d] = a;
}

// ---------------- per-point prep: xyzw + ksum ----------------
__global__ void k_prep(const float* __restrict__ xyz, const float* __restrict__ feat) {
    int warp = threadIdx.x >> 5, lane = threadIdx.x & 31;
    int p = blockIdx.x*8 + warp;
    const float* fr = feat + (size_t)p*D;
    float acc = 0.f;
    #pragma unroll
    for (int i = 0; i < 4; ++i) {
        int d = lane + 32*i;
        acc = fmaf(fr[d], g_wkrs[d], acc);
    }
    #pragma unroll
    for (int off = 16; off; off >>= 1) acc += __shfl_xor_sync(0xffffffffu, acc, off);
    if (lane == 0) {
        g_ksum[p] = acc;
        float x = xyz[3*p], y = xyz[3*p+1], z = xyz[3*p+2];
        g_xyzw[p] = make_float4(-2.f*x, -2.f*y, -2.f*z, x*x + y*y + z*z);
    }
}

// ---------------- brute-force kNN: 4 warps split the candidate dim ----------------
#define SPLIT 4
#define CHUNK (NPTS/SPLIT)   // 2048
#define QTILE 512

__global__ void __launch_bounds__(128) k_topk(const float* __restrict__ xyz) {
    __shared__ float4 tile[SPLIT][QTILE];    // 32KB candidate staging; reused for merge
    __shared__ float  sth[SPLIT][32];        // per-(warp,query) local 16th-best

    int w = threadIdx.x >> 5, lane = threadIdx.x & 31;
    int b = blockIdx.y;
    int q = blockIdx.x*32 + lane;            // lane == query slot, same for all warps
    int qg = b*NPTS + q;
    float qx = xyz[3*qg], qy = xyz[3*qg+1], qz = xyz[3*qg+2];

    sth[w][lane] = CUDART_INF_F;
    __syncthreads();

    float dist[KNN]; int nid[KNN];
    #pragma unroll
    for (int t = 0; t < KNN; ++t) { dist[t] = CUDART_INF_F; nid[t] = 0; }

    float st = CUDART_INF_F;                 // last-seen cross-warp threshold
    float thresh = CUDART_INF_F;
    float pkey = 0.f; int pidx = 0; bool pval = false;

    const float4* cand = g_xyzw + b*NPTS + w*CHUNK;
    for (int c0 = 0; c0 < CHUNK; c0 += QTILE) {
        __syncwarp();
        #pragma unroll
        for (int i = 0; i < QTILE/32; ++i)
            tile[w][lane + i*32] = cand[c0 + lane + i*32];
        __syncwarp();

        for (int t0 = 0; t0 < QTILE; t0 += 128) {
            // refresh cross-warp threshold (stale reads are safe: stale = larger)
            float s0 = *(volatile float*)&sth[0][lane];
            float s1 = *(volatile float*)&sth[1][lane];
            float s2 = *(volatile float*)&sth[2][lane];
            float s3 = *(volatile float*)&sth[3][lane];
            st = fminf(fminf(s0, s1), fminf(s2, s3));
            thresh = fminf(thresh, st);

            #pragma unroll 4
            for (int t = t0; t < t0 + 128; ++t) {
                float4 c = tile[w][t];
                // key = |c|^2 - 2*q.c  (dist - |q|^2, ordering-equivalent)
                float key = fmaf(c.x, qx, fmaf(c.y, qy, fmaf(c.z, qz, c.w)));
                bool hit = key < thresh;
                if (__any_sync(0xffffffffu, hit && pval)) {
                    // warp-uniform flush of pending entries
                    if (pval) {
                        float ck = pkey; int ci = pidx;
                        #pragma unroll
                        for (int s = 0; s < KNN; ++s) {
                            bool sw = (ck <= dist[s]);
                            float td = dist[s]; int ti = nid[s];
                            dist[s] = sw ? ck : td;  nid[s] = sw ? ci : ti;
                            ck = sw ? td : ck;       ci = sw ? ti : ci;
                        }
                        thresh = fminf(dist[KNN-1], st);
                    }
                    sth[w][lane] = dist[KNN-1];     // publish tightened bound
                    pval = false;
                }
                if (hit) { pkey = key; pidx = w*CHUNK + c0 + t; pval = true; }
            }
        }
    }
    // final per-lane flush (divergent, once)
    if (pval) {
        float ck = pkey; int ci = pidx;
        #pragma unroll
        for (int s = 0; s < KNN; ++s) {
            bool sw = (ck <= dist[s]);
            float td = dist[s]; int ti = nid[s];
            dist[s] = sw ? ck : td;  nid[s] = sw ? ci : ti;
            ck = sw ? td : ck;       ci = sw ? ti : ci;
        }
    }

    // ---- 4-way merge of sorted 16-lists (reuse tile smem, transposed layout) ----
    __syncthreads();
    float* md = (float*)&tile[0][0];            // md[s*128 + w*32 + lane]
    int*   mi = (int*)(md + KNN*128);
    #pragma unroll
    for (int s = 0; s < KNN; ++s) {
        md[s*128 + w*32 + lane] = dist[s];
        mi[s*128 + w*32 + lane] = nid[s];
    }
    __syncthreads();
    if (w == 0) {
        int p0 = 0, p1 = 0, p2 = 0, p3 = 0;
        int* op = g_idx + (size_t)qg*KNN;
        #pragma unroll
        for (int s = 0; s < KNN; ++s) {
            float h0 = md[p0*128 +  0 + lane];
            float h1 = md[p1*128 + 32 + lane];
            float h2 = md[p2*128 + 64 + lane];
            float h3 = md[p3*128 + 96 + lane];
            float best = h0; int bw = 0;
            if (h1 < best) { best = h1; bw = 1; }    // strict: lower chunk wins ties
            if (h2 < best) { best = h2; bw = 2; }
            if (h3 < best) { best = h3; bw = 3; }
            int pj = (bw == 0) ? p0 : (bw == 1) ? p1 : (bw == 2) ? p2 : p3;
            op[s] = mi[pj*128 + bw*32 + lane];
            if (bw == 0) ++p0; else if (bw == 1) ++p1; else if (bw == 2) ++p2; else ++p3;
        }
    }
}

// ---------------- v = feat @ Wv + bv ----------------
__global__ void k_gemm_v(const float* __restrict__ feat, const float* __restrict__ Wv,
                         const float* __restrict__ bv) {
    __shared__ float As[16][132];
    __shared__ float Ws[16][132];
    int m0 = blockIdx.x*128;
    int tx = threadIdx.x & 15, ty = threadIdx.x >> 4;
    float acc[8][8];
    #pragma unroll
    for (int i = 0; i < 8; ++i)
        #pragma unroll
        for (int j = 0; j < 8; ++j) acc[i][j] = 0.f;

    for (int kc = 0; kc < D; kc += 16) {
        __syncthreads();
        { // A chunk transposed into As[k][m]
            int c = threadIdx.x & 3, r = threadIdx.x >> 2;
            #pragma unroll
            for (int rr = 0; rr < 2; ++rr) {
                int mm = r + rr*64;
                float4 v = *(const float4*)&feat[(size_t)(m0+mm)*D + kc + c*4];
                As[c*4+0][mm] = v.x; As[c*4+1][mm] = v.y;
                As[c*4+2][mm] = v.z; As[c*4+3][mm] = v.w;
            }
        }
        { // W chunk
            int k = threadIdx.x >> 5, c4 = threadIdx.x & 31;
            #pragma unroll
            for (int kk = 0; kk < 2; ++kk) {
                float4 v = *(const float4*)&Wv[(size_t)(kc + k + kk*8)*D + c4*4];
                Ws[k + kk*8][c4*4+0] = v.x; Ws[k + kk*8][c4*4+1] = v.y;
                Ws[k + kk*8][c4*4+2] = v.z; Ws[k + kk*8][c4*4+3] = v.w;
            }
        }
        __syncthreads();
        #pragma unroll
        for (int k = 0; k < 16; ++k) {
            float a[8], bb[8];
            #pragma unroll
            for (int i = 0; i < 8; ++i) a[i]  = As[k][ty*8 + i];
            #pragma unroll
            for (int j = 0; j < 8; ++j) bb[j] = Ws[k][tx*8 + j];
            #pragma unroll
            for (int i = 0; i < 8; ++i)
                #pragma unroll
                for (int j = 0; j < 8; ++j) acc[i][j] = fmaf(a[i], bb[j], acc[i][j]);
        }
    }
    #pragma unroll
    for (int i = 0; i < 8; ++i) {
        int m = m0 + ty*8 + i;
        #pragma unroll
        for (int j = 0; j < 8; ++j) acc[i][j] += bv[tx*8 + j];
        *(float4*)&g_v[(size_t)m*D + tx*8]     = make_float4(acc[i][0], acc[i][1], acc[i][2], acc[i][3]);
        *(float4*)&g_v[(size_t)m*D + tx*8 + 4] = make_float4(acc[i][4], acc[i][5], acc[i][6], acc[i][7]);
    }
}

// ---------------- fused attention (warp per point) ----------------
__global__ void k_fuse(const float* __restrict__ xyz, const float* __restrict__ Wp1,
                       const float* __restrict__ bp1) {
    __shared__ float sw0[D], sw1[D], sw2[D], sb1[D], srs[D];
    int tid = threadIdx.x;
    sw0[tid] = Wp1[tid]; sw1[tid] = Wp1[D + tid]; sw2[tid] = Wp1[2*D + tid];
    sb1[tid] = bp1[tid]; srs[tid] = g_wp2rs[tid];
    __syncthreads();

    int warp = tid >> 5, lane = tid & 31;
    int p = blockIdx.x*4 + warp;
    int bbase = p & ~(NPTS-1);   // b*NPTS

    float w0[4], w1[4], w2[4], b1r[4], rs[4];
    #pragma unroll
    for (int i = 0; i < 4; ++i) {
        int d = lane + 32*i;
        w0[i] = sw0[d]; w1[i] = sw1[d]; w2[i] = sw2[d]; b1r[i] = sb1[d]; rs[i] = srs[d];
    }

    float rx = 0.f, ry = 0.f, rz = 0.f, ks = 0.f; int row = 0;
    if (lane < KNN) {
        int nb = g_idx[(size_t)p*KNN + lane];
        row = bbase + nb;
        float qx = xyz[3*p], qy = xyz[3*p+1], qz = xyz[3*p+2];
        rx = qx - xyz[3*row]; ry = qy - xyz[3*row+1]; rz = qz - xyz[3*row+2];
        ks = g_ksum[row];
    }

    // pass 1: attention logits  score_k = h_k . rowsum(Wp2) - ksum_k
    float mysc = -CUDART_INF_F;
    #pragma unroll
    for (int k = 0; k < KNN; ++k) {
        float bx = __shfl_sync(0xffffffffu, rx, k);
        float by = __shfl_sync(0xffffffffu, ry, k);
        float bz = __shfl_sync(0xffffffffu, rz, k);
        float part = 0.f;
        #pragma unroll
        for (int i = 0; i < 4; ++i) {
            float h = fmaf(bx, w0[i], fmaf(by, w1[i], fmaf(bz, w2[i], b1r[i])));
            h = fmaxf(h, 0.f);
            part = fmaf(h, rs[i], part);
        }
        #pragma unroll
        for (int off = 16; off; off >>= 1) part += __shfl_xor_sync(0xffffffffu, part, off);
        if (lane == k) mysc = part - ks;
    }
    // softmax over the 16 neighbor lanes
    float mx = mysc;
    #pragma unroll
    for (int off = 16; off; off >>= 1) mx = fmaxf(mx, __shfl_xor_sync(0xffffffffu, mx, off));
    float e = (lane < KNN) ? __expf(mysc - mx) : 0.f;
    float ssum = e;
    #pragma unroll
    for (int off = 16; off; off >>= 1) ssum += __shfl_xor_sync(0xffffffffu, ssum, off);
    float attn = e / ssum;

    // pass 2: hbar = sum attn*h, vbar = sum attn*v
    float hb[4] = {0,0,0,0}, vb[4] = {0,0,0,0};
    #pragma unroll
    for (int k = 0; k < KNN; ++k) {
        float a  = __shfl_sync(0xffffffffu, attn, k);
        float bx = __shfl_sync(0xffffffffu, rx, k);
        float by = __shfl_sync(0xffffffffu, ry, k);
        float bz = __shfl_sync(0xffffffffu, rz, k);
        int   r  = __shfl_sync(0xffffffffu, row, k);
        const float* vr = g_v + (size_t)r*D;
        #pragma unroll
        for (int i = 0; i < 4; ++i) {
            int d = lane + 32*i;
            float h = fmaf(bx, w0[i], fmaf(by, w1[i], fmaf(bz, w2[i], b1r[i])));
            h = fmaxf(h, 0.f);
            hb[i] = fmaf(a, h, hb[i]);
            vb[i] = fmaf(a, vr[d], vb[i]);
        }
    }
    #pragma unroll
    for (int i = 0; i < 4; ++i) {
        int d = lane + 32*i;
        g_hbar[(size_t)p*D + d] = hb[i];
        g_vbar[(size_t)p*D + d] = vb[i];
    }
}

// ---------------- out = feat + gamma*(vbar@Wo + hbar@Wf + cvec) ----------------
__global__ void k_out(const float* __restrict__ feat, const float* __restrict__ Wo,
                      const float* __restrict__ gamma, float* __restrict__ out) {
    __shared__ float As[16][132];
    __shared__ float Ws[16][132];
    int m0 = blockIdx.x*128;
    int tx = threadIdx.x & 15, ty = threadIdx.x >> 4;
    float acc[8][8];
    #pragma unroll
    for (int i = 0; i < 8; ++i)
        #pragma unroll
        for (int j = 0; j < 8; ++j) acc[i][j] = 0.f;

    for (int ph = 0; ph < 2; ++ph) {
        const float* A = ph ? g_hbar : g_vbar;
        const float* W = ph ? g_wf   : Wo;
        for (int kc = 0; kc < D; kc += 16) {
            __syncthreads();
            { int c = threadIdx.x & 3, r = threadIdx.x >> 2;
              #pragma unroll
              for (int rr = 0; rr < 2; ++rr) {
                  int mm = r + rr*64;
                  float4 v = *(const float4*)&A[(size_t)(m0+mm)*D + kc + c*4];
                  As[c*4+0][mm] = v.x; As[c*4+1][mm] = v.y;
                  As[c*4+2][mm] = v.z; As[c*4+3][mm] = v.w;
              }
            }
            { int k = threadIdx.x >> 5, c4 = threadIdx.x & 31;
              #pragma unroll
              for (int kk = 0; kk < 2; ++kk) {
                  float4 v = *(const float4*)&W[(size_t)(kc + k + kk*8)*D + c4*4];
                  Ws[k + kk*8][c4*4+0] = v.x; Ws[k + kk*8][c4*4+1] = v.y;
                  Ws[k + kk*8][c4*4+2] = v.z; Ws[k + kk*8][c4*4+3] = v.w;
              }
            }
            __syncthreads();
            #pragma unroll
            for (int k = 0; k < 16; ++k) {
                float a[8], bb[8];
                #pragma unroll
                for (int i = 0; i < 8; ++i) a[i]  = As[k][ty*8 + i];
                #pragma unroll
                for (int j = 0; j < 8; ++j) bb[j] = Ws[k][tx*8 + j];
                #pragma unroll
                for (int i = 0; i < 8; ++i)
                    #pragma unroll
                    for (int j = 0; j < 8; ++j) acc[i][j] = fmaf(a[i], bb[j], acc[i][j]);
            }
        }
    }
    float g = *gamma;
    float cv[8];
    #pragma unroll
    for (int j = 0; j < 8; ++j) cv[j] = g_cvec[tx*8 + j];
    #pragma unroll
    for (int i = 0; i < 8; ++i) {
        int m = m0 + ty*8 + i;
        float4 f0 = *(const float4*)&feat[(size_t)m*D + tx*8];
        float4 f1 = *(const float4*)&feat[(size_t)m*D + tx*8 + 4];
        float o0 = f0.x + g*(acc[i][0] + cv[0]);
        float o1 = f0.y + g*(acc[i][1] + cv[1]);
        float o2 = f0.z + g*(acc[i][2] + cv[2]);
        float o3 = f0.w + g*(acc[i][3] + cv[3]);
        float o4 = f1.x + g*(acc[i][4] + cv[4]);
        float o5 = f1.y + g*(acc[i][5] + cv[5]);
        float o6 = f1.z + g*(acc[i][6] + cv[6]);
        float o7 = f1.w + g*(acc[i][7] + cv[7]);
        *(float4*)&out[(size_t)m*D + tx*8]     = make_float4(o0, o1, o2, o3);
        *(float4*)&out[(size_t)m*D + tx*8 + 4] = make_float4(o4, o5, o6, o7);
    }
}

// ---------------- launch ----------------
extern "C" void kernel_launch(void* const* d_in, const int* in_sizes, int n_in,
                              void* d_out, int out_size) {
    const float* xyz  = (const float*)d_in[0];
    const float* feat = (const float*)d_in[1];
    // d_in[2]=Wq, d_in[3]=bq, d_in[5]=bk : mathematically cancel in softmax, unused
    const float* Wk   = (const float*)d_in[4];
    const float* Wv   = (const float*)d_in[6];
    const float* bv   = (const float*)d_in[7];
    const float* Wp1  = (const float*)d_in[8];
    const float* bp1  = (const float*)d_in[9];
    const float* Wp2  = (const float*)d_in[10];
    const float* bp2  = (const float*)d_in[11];
    const float* Wo   = (const float*)d_in[12];
    const float* bo   = (const float*)d_in[13];
    const float* gmm  = (const float*)d_in[14];
    float* out = (float*)d_out;

    k_weights<<<1, 128>>>(Wk, Wp2, bp2, Wo, bo);
    k_wfused<<<64, 256>>>(Wp2, Wo);
    k_prep<<<BN/8, 256>>>(xyz, feat);
    k_topk<<<dim3(NPTS/32, NB), 128>>>(xyz);
    k_gemm_v<<<BN/128, 256>>>(feat, Wv, bv);
    k_fuse<<<BN/4, 128>>>(xyz, Wp1, bp1);
    k_out<<<BN/128, 256>>>(feat, Wo, gmm, out);
}

// round 4
// speedup vs baseline: 1.6300x; 1.1068x over previous
#include <cuda_runtime.h>
#include <math.h>
#include <math_constants.h>

#define NB   4
#define NPTS 8192
#define BN   (NB*NPTS)   // 32768
#define D    128
#define KNN  16

// ---------------- scratch (static device allocations) ----------------
__device__ float4 g_xyzw[BN];          // (-2x,-2y,-2z, |x|^2) per point
__device__ float  g_ksum[BN];          // feat . rowsum(Wk)
__device__ int    g_idx[BN*KNN];       // knn indices (within batch)
__device__ float  g_v[BN*D];           // feat @ Wv + bv
__device__ float  g_hbar[BN*D];        // sum_k attn_k * h_k
__device__ float  g_vbar[BN*D];        // sum_k attn_k * v_k
__device__ float  g_wkrs[D];           // rowsum over out-dim of Wk
__device__ float  g_wp2rs[D];          // rowsum over out-dim of Wp2
__device__ float  g_cvec[D];           // bp2 @ Wo + bo
__device__ float  g_wf[D*D];           // Wp2 @ Wo

// ---------------- weight prep (merged) ----------------
__global__ void k_weights(const float* __restrict__ Wk, const float* __restrict__ Wp2,
                          const float* __restrict__ bp2, const float* __restrict__ Wo,
                          const float* __restrict__ bo) {
    int i = threadIdx.x;
    float a = 0.f, b = 0.f, c = bo[i];
    for (int j = 0; j < D; ++j) { a += Wk[i*D + j]; b += Wp2[i*D + j]; }
    for (int k = 0; k < D; ++k) c = fmaf(bp2[k], Wo[k*D + i], c);
    g_wkrs[i] = a; g_wp2rs[i] = b; g_cvec[i] = c;
}

__global__ void k_wfused(const float* __restrict__ Wp2, const float* __restrict__ Wo) {
    int d = threadIdx.x & (D-1);
    int i = blockIdx.x*2 + (threadIdx.x >> 7);
    float a = 0.f;
    for (int k = 0; k < D; ++k) a = fmaf(Wp2[i*D + k], Wo[k*D + d], a);
    g_wf[i*D + d] = a;
}

// ---------------- per-point prep: xyzw + ksum ----------------
__global__ void k_prep(const float* __restrict__ xyz, const float* __restrict__ feat) {
    int warp = threadIdx.x >> 5, lane = threadIdx.x & 31;
    int p = blockIdx.x*8 + warp;
    const float* fr = feat + (size_t)p*D;
    float acc = 0.f;
    #pragma unroll
    for (int i = 0; i < 4; ++i) {
        int d = lane + 32*i;
        acc = fmaf(fr[d], g_wkrs[d], acc);
    }
    #pragma unroll
    for (int off = 16; off; off >>= 1) acc += __shfl_xor_sync(0xffffffffu, acc, off);
    if (lane == 0) {
        g_ksum[p] = acc;
        float x = xyz[3*p], y = xyz[3*p+1], z = xyz[3*p+2];
        g_xyzw[p] = make_float4(-2.f*x, -2.f*y, -2.f*z, x*x + y*y + z*z);
    }
}

// ---------------- brute-force kNN: packed (dist|idx) keys, IMNMX inserts ----------------
#define SPLIT 8
#define CHUNK (NPTS/SPLIT)   // 1024
#define QTILE 256
#define IDXMASK 0x3FFu       // 10 bits: CHUNK-local candidate index

__global__ void __launch_bounds__(256) k_topk(const float* __restrict__ xyz) {
    __shared__ float4   tile[SPLIT][QTILE];     // 32KB candidate staging
    __shared__ unsigned sth[SPLIT][32];         // per-(warp,query) local 16th-best (packed)
    __shared__ unsigned mm[KNN*SPLIT*32];       // 16KB: mm[s*256 + w*32 + lane]

    int w = threadIdx.x >> 5, lane = threadIdx.x & 31;
    int b = blockIdx.y;
    int q = blockIdx.x*32 + lane;               // lane == query slot
    int qg = b*NPTS + q;
    float qx = xyz[3*qg], qy = xyz[3*qg+1], qz = xyz[3*qg+2];
    float qw = g_xyzw[qg].w;                    // |q|^2 (exact, matches prep)

    sth[w][lane] = 0xFFFFFFFFu;
    __syncthreads();

    unsigned a[KNN];
    #pragma unroll
    for (int t = 0; t < KNN; ++t) a[t] = 0xFFFFFFFFu;

    unsigned st = 0xFFFFFFFFu, thresh = 0xFFFFFFFFu;
    unsigned ppack = 0; bool pval = false;

    const float4* cand = g_xyzw + b*NPTS + w*CHUNK;
    for (int c0 = 0; c0 < CHUNK; c0 += QTILE) {
        __syncwarp();
        #pragma unroll
        for (int i = 0; i < QTILE/32; ++i)
            tile[w][lane + i*32] = cand[c0 + lane + i*32];
        __syncwarp();

        for (int t0 = 0; t0 < QTILE; t0 += 64) {
            // refresh cross-warp threshold (stale reads safe: stale = larger)
            unsigned s_ = 0xFFFFFFFFu;
            #pragma unroll
            for (int ww = 0; ww < SPLIT; ++ww)
                s_ = umin(s_, *(volatile unsigned*)&sth[ww][lane]);
            st = s_;
            thresh = umin(thresh, st);

            #pragma unroll 4
            for (int t = t0; t < t0 + 64; ++t) {
                float4 c = tile[w][t];
                // dist = |c-q|^2 (>=0 after clamp); positive fp32 sorts as uint
                float dist = fmaxf(fmaf(c.x, qx, fmaf(c.y, qy, fmaf(c.z, qz, c.w))) + qw, 0.f);
                unsigned pk = (__float_as_uint(dist) & ~IDXMASK) | (unsigned)(c0 + t);
                bool hit = pk < thresh;          // strict uint: lower idx wins ties
                if (__any_sync(0xffffffffu, hit && pval)) {
                    if (pval) {                  // warp-uniform flush, pure IMNMX chain
                        unsigned ck = ppack;
                        #pragma unroll
                        for (int s = 0; s < KNN; ++s) {
                            unsigned lo = umin(ck, a[s]);
                            ck = umax(ck, a[s]);
                            a[s] = lo;
                        }
                        thresh = umin(a[KNN-1], st);
                    }
                    sth[w][lane] = a[KNN-1];     // publish tightened bound
                    pval = false;
                }
                if (hit) { ppack = pk; pval = true; }
            }
        }
    }
    if (pval) {                                  // final flush
        unsigned ck = ppack;
        #pragma unroll
        for (int s = 0; s < KNN; ++s) {
            unsigned lo = umin(ck, a[s]); ck = umax(ck, a[s]); a[s] = lo;
        }
    }

    // ---- 8-way merge of sorted 16-lists ----
    #pragma unroll
    for (int s = 0; s < KNN; ++s) mm[s*(SPLIT*32) + w*32 + lane] = a[s];
    __syncthreads();
    if (w == 0) {
        int p0=0,p1=0,p2=0,p3=0,p4=0,p5=0,p6=0,p7=0;
        int* op = g_idx + (size_t)qg*KNN;
        #pragma unroll
        for (int s = 0; s < KNN; ++s) {
            unsigned h0 = mm[p0*256 +   0 + lane];
            unsigned h1 = mm[p1*256 +  32 + lane];
            unsigned h2 = mm[p2*256 +  64 + lane];
            unsigned h3 = mm[p3*256 +  96 + lane];
            unsigned h4 = mm[p4*256 + 128 + lane];
            unsigned h5 = mm[p5*256 + 160 + lane];
            unsigned h6 = mm[p6*256 + 192 + lane];
            unsigned h7 = mm[p7*256 + 224 + lane];
            unsigned best = h0; int bw = 0;
            if (h1 < best) { best = h1; bw = 1; }
            if (h2 < best) { best = h2; bw = 2; }
            if (h3 < best) { best = h3; bw = 3; }
            if (h4 < best) { best = h4; bw = 4; }
            if (h5 < best) { best = h5; bw = 5; }
            if (h6 < best) { best = h6; bw = 6; }
            if (h7 < best) { best = h7; bw = 7; }
            op[s] = (int)(best & IDXMASK) + bw*CHUNK;
            p0 += (bw==0); p1 += (bw==1); p2 += (bw==2); p3 += (bw==3);
            p4 += (bw==4); p5 += (bw==5); p6 += (bw==6); p7 += (bw==7);
        }
    }
}

// ---------------- v = feat @ Wv + bv ----------------
__global__ void k_gemm_v(const float* __restrict__ feat, const float* __restrict__ Wv,
                         const float* __restrict__ bv) {
    __shared__ float As[16][132];
    __shared__ float Ws[16][132];
    int m0 = blockIdx.x*128;
    int tx = threadIdx.x & 15, ty = threadIdx.x >> 4;
    float acc[8][8];
    #pragma unroll
    for (int i = 0; i < 8; ++i)
        #pragma unroll
        for (int j = 0; j < 8; ++j) acc[i][j] = 0.f;

    for (int kc = 0; kc < D; kc += 16) {
        __syncthreads();
        { // A chunk transposed into As[k][m]
            int c = threadIdx.x & 3, r = threadIdx.x >> 2;
            #pragma unroll
            for (int rr = 0; rr < 2; ++rr) {
                int mm = r + rr*64;
                float4 v = *(const float4*)&feat[(size_t)(m0+mm)*D + kc + c*4];
                As[c*4+0][mm] = v.x; As[c*4+1][mm] = v.y;
                As[c*4+2][mm] = v.z; As[c*4+3][mm] = v.w;
            }
        }
        { // W chunk
            int k = threadIdx.x >> 5, c4 = threadIdx.x & 31;
            #pragma unroll
            for (int kk = 0; kk < 2; ++kk) {
                float4 v = *(const float4*)&Wv[(size_t)(kc + k + kk*8)*D + c4*4];
                Ws[k + kk*8][c4*4+0] = v.x; Ws[k + kk*8][c4*4+1] = v.y;
                Ws[k + kk*8][c4*4+2] = v.z; Ws[k + kk*8][c4*4+3] = v.w;
            }
        }
        __syncthreads();
        #pragma unroll
        for (int k = 0; k < 16; ++k) {
            float a[8], bb[8];
            #pragma unroll
            for (int i = 0; i < 8; ++i) a[i]  = As[k][ty*8 + i];
            #pragma unroll
            for (int j = 0; j < 8; ++j) bb[j] = Ws[k][tx*8 + j];
            #pragma unroll
            for (int i = 0; i < 8; ++i)
                #pragma unroll
                for (int j = 0; j < 8; ++j) acc[i][j] = fmaf(a[i], bb[j], acc[i][j]);
        }
    }
    #pragma unroll
    for (int i = 0; i < 8; ++i) {
        int m = m0 + ty*8 + i;
        #pragma unroll
        for (int j = 0; j < 8; ++j) acc[i][j] += bv[tx*8 + j];
        *(float4*)&g_v[(size_t)m*D + tx*8]     = make_float4(acc[i][0], acc[i][1], acc[i][2], acc[i][3]);
        *(float4*)&g_v[(size_t)m*D + tx*8 + 4] = make_float4(acc[i][4], acc[i][5], acc[i][6], acc[i][7]);
    }
}

// ---------------- fused attention (warp per point) ----------------
__global__ void k_fuse(const float* __restrict__ xyz, const float* __restrict__ Wp1,
                       const float* __restrict__ bp1) {
    __shared__ float sw0[D], sw1[D], sw2[D], sb1[D], srs[D];
    int tid = threadIdx.x;
    sw0[tid] = Wp1[tid]; sw1[tid] = Wp1[D + tid]; sw2[tid] = Wp1[2*D + tid];
    sb1[tid] = bp1[tid]; srs[tid] = g_wp2rs[tid];
    __syncthreads();

    int warp = tid >> 5, lane = tid & 31;
    int p = blockIdx.x*4 + warp;
    int bbase = p & ~(NPTS-1);   // b*NPTS

    float w0[4], w1[4], w2[4], b1r[4], rs[4];
    #pragma unroll
    for (int i = 0; i < 4; ++i) {
        int d = lane + 32*i;
        w0[i] = sw0[d]; w1[i] = sw1[d]; w2[i] = sw2[d]; b1r[i] = sb1[d]; rs[i] = srs[d];
    }

    float rx = 0.f, ry = 0.f, rz = 0.f, ks = 0.f; int row = 0;
    if (lane < KNN) {
        int nb = g_idx[(size_t)p*KNN + lane];
        row = bbase + nb;
        float qx = xyz[3*p], qy = xyz[3*p+1], qz = xyz[3*p+2];
        rx = qx - xyz[3*row]; ry = qy - xyz[3*row+1]; rz = qz - xyz[3*row+2];
        ks = g_ksum[row];
    }

    // pass 1: attention logits  score_k = h_k . rowsum(Wp2) - ksum_k
    float mysc = -CUDART_INF_F;
    #pragma unroll
    for (int k = 0; k < KNN; ++k) {
        float bx = __shfl_sync(0xffffffffu, rx, k);
        float by = __shfl_sync(0xffffffffu, ry, k);
        float bz = __shfl_sync(0xffffffffu, rz, k);
        float part = 0.f;
        #pragma unroll
        for (int i = 0; i < 4; ++i) {
            float h = fmaf(bx, w0[i], fmaf(by, w1[i], fmaf(bz, w2[i], b1r[i])));
            h = fmaxf(h, 0.f);
            part = fmaf(h, rs[i], part);
        }
        #pragma unroll
        for (int off = 16; off; off >>= 1) part += __shfl_xor_sync(0xffffffffu, part, off);
        if (lane == k) mysc = part - ks;
    }
    // softmax over the 16 neighbor lanes
    float mx = mysc;
    #pragma unroll
    for (int off = 16; off; off >>= 1) mx = fmaxf(mx, __shfl_xor_sync(0xffffffffu, mx, off));
    float e = (lane < KNN) ? __expf(mysc - mx) : 0.f;
    float ssum = e;
    #pragma unroll
    for (int off = 16; off; off >>= 1) ssum += __shfl_xor_sync(0xffffffffu, ssum, off);
    float attn = e / ssum;

    // pass 2: hbar = sum attn*h, vbar = sum attn*v
    float hb[4] = {0,0,0,0}, vb[4] = {0,0,0,0};
    #pragma unroll
    for (int k = 0; k < KNN; ++k) {
        float a  = __shfl_sync(0xffffffffu, attn, k);
        float bx = __shfl_sync(0xffffffffu, rx, k);
        float by = __shfl_sync(0xffffffffu, ry, k);
        float bz = __shfl_sync(0xffffffffu, rz, k);
        int   r  = __shfl_sync(0xffffffffu, row, k);
        const float* vr = g_v + (size_t)r*D;
        #pragma unroll
        for (int i = 0; i < 4; ++i) {
            int d = lane + 32*i;
            float h = fmaf(bx, w0[i], fmaf(by, w1[i], fmaf(bz, w2[i], b1r[i])));
            h = fmaxf(h, 0.f);
            hb[i] = fmaf(a, h, hb[i]);
            vb[i] = fmaf(a, vr[d], vb[i]);
        }
    }
    #pragma unroll
    for (int i = 0; i < 4; ++i) {
        int d = lane + 32*i;
        g_hbar[(size_t)p*D + d] = hb[i];
        g_vbar[(size_t)p*D + d] = vb[i];
    }
}

// ---------------- out = feat + gamma*(vbar@Wo + hbar@Wf + cvec) ----------------
__global__ void k_out(const float* __restrict__ feat, const float* __restrict__ Wo,
                      const float* __restrict__ gamma, float* __restrict__ out) {
    __shared__ float As[16][132];
    __shared__ float Ws[16][132];
    int m0 = blockIdx.x*128;
    int tx = threadIdx.x & 15, ty = threadIdx.x >> 4;
    float acc[8][8];
    #pragma unroll
    for (int i = 0; i < 8; ++i)
        #pragma unroll
        for (int j = 0; j < 8; ++j) acc[i][j] = 0.f;

    for (int ph = 0; ph < 2; ++ph) {
        const float* A = ph ? g_hbar : g_vbar;
        const float* W = ph ? g_wf   : Wo;
        for (int kc = 0; kc < D; kc += 16) {
            __syncthreads();
            { int c = threadIdx.x & 3, r = threadIdx.x >> 2;
              #pragma unroll
              for (int rr = 0; rr < 2; ++rr) {
                  int mm = r + rr*64;
                  float4 v = *(const float4*)&A[(size_t)(m0+mm)*D + kc + c*4];
                  As[c*4+0][mm] = v.x; As[c*4+1][mm] = v.y;
                  As[c*4+2][mm] = v.z; As[c*4+3][mm] = v.w;
              }
            }
            { int k = threadIdx.x >> 5, c4 = threadIdx.x & 31;
              #pragma unroll
              for (int kk = 0; kk < 2; ++kk) {
                  float4 v = *(const float4*)&W[(size_t)(kc + k + kk*8)*D + c4*4];
                  Ws[k + kk*8][c4*4+0] = v.x; Ws[k + kk*8][c4*4+1] = v.y;
                  Ws[k + kk*8][c4*4+2] = v.z; Ws[k + kk*8][c4*4+3] = v.w;
              }
            }
            __syncthreads();
            #pragma unroll
            for (int k = 0; k < 16; ++k) {
                float a[8], bb[8];
                #pragma unroll
                for (int i = 0; i < 8; ++i) a[i]  = As[k][ty*8 + i];
                #pragma unroll
                for (int j = 0; j < 8; ++j) bb[j] = Ws[k][tx*8 + j];
                #pragma unroll
                for (int i = 0; i < 8; ++i)
                    #pragma unroll
                    for (int j = 0; j < 8; ++j) acc[i][j] = fmaf(a[i], bb[j], acc[i][j]);
            }
        }
    }
    float g = *gamma;
    float cv[8];
    #pragma unroll
    for (int j = 0; j < 8; ++j) cv[j] = g_cvec[tx*8 + j];
    #pragma unroll
    for (int i = 0; i < 8; ++i) {
        int m = m0 + ty*8 + i;
        float4 f0 = *(const float4*)&feat[(size_t)m*D + tx*8];
        float4 f1 = *(const float4*)&feat[(size_t)m*D + tx*8 + 4];
        float o0 = f0.x + g*(acc[i][0] + cv[0]);
        float o1 = f0.y + g*(acc[i][1] + cv[1]);
        float o2 = f0.z + g*(acc[i][2] + cv[2]);
        float o3 = f0.w + g*(acc[i][3] + cv[3]);
        float o4 = f1.x + g*(acc[i][4] + cv[4]);
        float o5 = f1.y + g*(acc[i][5] + cv[5]);
        float o6 = f1.z + g*(acc[i][6] + cv[6]);
        float o7 = f1.w + g*(acc[i][7] + cv[7]);
        *(float4*)&out[(size_t)m*D + tx*8]     = make_float4(o0, o1, o2, o3);
        *(float4*)&out[(size_t)m*D + tx*8 + 4] = make_float4(o4, o5, o6, o7);
    }
}

// ---------------- launch ----------------
extern "C" void kernel_launch(void* const* d_in, const int* in_sizes, int n_in,
                              void* d_out, int out_size) {
    const float* xyz  = (const float*)d_in[0];
    const float* feat = (const float*)d_in[1];
    // d_in[2]=Wq, d_in[3]=bq, d_in[5]=bk : mathematically cancel in softmax, unused
    const float* Wk   = (const float*)d_in[4];
    const float* Wv   = (const float*)d_in[6];
    const float* bv   = (const float*)d_in[7];
    const float* Wp1  = (const float*)d_in[8];
    const float* bp1  = (const float*)d_in[9];
    const float* Wp2  = (const float*)d_in[10];
    const float* bp2  = (const float*)d_in[11];
    const float* Wo   = (const float*)d_in[12];
    const float* bo   = (const float*)d_in[13];
    const float* gmm  = (const float*)d_in[14];
    float* out = (float*)d_out;

    k_weights<<<1, 128>>>(Wk, Wp2, bp2, Wo, bo);
    k_wfused<<<64, 256>>>(Wp2, Wo);
    k_prep<<<BN/8, 256>>>(xyz, feat);
    k_topk<<<dim3(NPTS/32, NB), 256>>>(xyz);
    k_gemm_v<<<BN/128, 256>>>(feat, Wv, bv);
    k_fuse<<<BN/4, 128>>>(xyz, Wp1, bp1);
    k_out<<<BN/128, 256>>>(feat, Wo, gmm, out);
}

// round 5
// speedup vs baseline: 1.7466x; 1.0715x over previous
#include <cuda_runtime.h>
#include <math.h>
#include <math_constants.h>

#define NB   4
#define NPTS 8192
#define BN   (NB*NPTS)   // 32768
#define D    128
#define KNN  16

// ---------------- scratch (static device allocations) ----------------
__device__ float4 g_xyzw[BN];          // (-2x,-2y,-2z, |x|^2 + eps) per point
__device__ float  g_ksum[BN];          // feat . rowsum(Wk)
__device__ int    g_idx[BN*KNN];       // knn indices (within batch)
__device__ float  g_v[BN*D];           // feat @ Wv + bv
__device__ float  g_hbar[BN*D];        // sum_k attn_k * h_k
__device__ float  g_vbar[BN*D];        // sum_k attn_k * v_k
__device__ float  g_wkrs[D];           // rowsum over out-dim of Wk
__device__ float  g_wp2rs[D];          // rowsum over out-dim of Wp2
__device__ float  g_cvec[D];           // bp2 @ Wo + bo
__device__ float  g_wf[D*D];           // Wp2 @ Wo

// ---------------- weight prep (merged) ----------------
__global__ void k_weights(const float* __restrict__ Wk, const float* __restrict__ Wp2,
                          const float* __restrict__ bp2, const float* __restrict__ Wo,
                          const float* __restrict__ bo) {
    int i = threadIdx.x;
    float a = 0.f, b = 0.f, c = bo[i];
    for (int j = 0; j < D; ++j) { a += Wk[i*D + j]; b += Wp2[i*D + j]; }
    for (int k = 0; k < D; ++k) c = fmaf(bp2[k], Wo[k*D + i], c);
    g_wkrs[i] = a; g_wp2rs[i] = b; g_cvec[i] = c;
}

__global__ void k_wfused(const float* __restrict__ Wp2, const float* __restrict__ Wo) {
    int d = threadIdx.x & (D-1);
    int i = blockIdx.x*2 + (threadIdx.x >> 7);
    float a = 0.f;
    for (int k = 0; k < D; ++k) a = fmaf(Wp2[i*D + k], Wo[k*D + d], a);
    g_wf[i*D + d] = a;
}

// ---------------- per-point prep: xyzw + ksum ----------------
#define DEPS 0.0009765625f   // 2^-10 positivity bias (uniform shift, order-preserving)
__global__ void k_prep(const float* __restrict__ xyz, const float* __restrict__ feat) {
    int warp = threadIdx.x >> 5, lane = threadIdx.x & 31;
    int p = blockIdx.x*8 + warp;
    const float* fr = feat + (size_t)p*D;
    float acc = 0.f;
    #pragma unroll
    for (int i = 0; i < 4; ++i) {
        int d = lane + 32*i;
        acc = fmaf(fr[d], g_wkrs[d], acc);
    }
    #pragma unroll
    for (int off = 16; off; off >>= 1) acc += __shfl_xor_sync(0xffffffffu, acc, off);
    if (lane == 0) {
        g_ksum[p] = acc;
        float x = xyz[3*p], y = xyz[3*p+1], z = xyz[3*p+2];
        g_xyzw[p] = make_float4(-2.f*x, -2.f*y, -2.f*z, x*x + y*y + z*z + DEPS);
    }
}

// ---------------- brute-force kNN: float fast path, pack at flush ----------------
#define SPLIT 8
#define CHUNK (NPTS/SPLIT)   // 1024
#define QTILE 256
#define IDXMASK 0x3FFu       // 10 bits: CHUNK-local candidate index

__device__ __forceinline__ float thr_from(unsigned thresh, float qw) {
    float tup = __uint_as_float(umin(thresh | IDXMASK, 0x7F7FFFFFu)); // avoid NaN bits
    return tup - qw + 1e-4f;   // conservative superset margin
}

__global__ void __launch_bounds__(256) k_topk(const float* __restrict__ xyz) {
    __shared__ float4   tile[SPLIT][QTILE];     // 32KB candidate staging
    __shared__ unsigned sth[SPLIT][32];         // per-(warp,query) local 16th-best (packed)
    __shared__ unsigned mm[KNN*SPLIT*32];       // 16KB merge buffer

    int w = threadIdx.x >> 5, lane = threadIdx.x & 31;
    int b = blockIdx.y;
    int q = blockIdx.x*32 + lane;               // lane == query slot
    int qg = b*NPTS + q;
    float qx = xyz[3*qg], qy = xyz[3*qg+1], qz = xyz[3*qg+2];
    float qw = g_xyzw[qg].w;                    // |q|^2 + eps

    sth[w][lane] = 0xFFFFFFFFu;
    __syncthreads();

    unsigned a[KNN];
    #pragma unroll
    for (int t = 0; t < KNN; ++t) a[t] = 0xFFFFFFFFu;

    unsigned st = 0xFFFFFFFFu, thresh = 0xFFFFFFFFu;
    float thrp = CUDART_INF_F;
    float pkey = 0.f; unsigned pidx = 0; bool pval = false;

    const float4* cand = g_xyzw + b*NPTS + w*CHUNK;
    for (int c0 = 0; c0 < CHUNK; c0 += QTILE) {
        __syncwarp();
        #pragma unroll
        for (int i = 0; i < QTILE/32; ++i)
            tile[w][lane + i*32] = cand[c0 + lane + i*32];
        __syncwarp();

        for (int t0 = 0; t0 < QTILE; t0 += 64) {
            // refresh cross-warp threshold (stale reads safe: stale = larger)
            unsigned s_ = 0xFFFFFFFFu;
            #pragma unroll
            for (int ww = 0; ww < SPLIT; ++ww)
                s_ = umin(s_, *(volatile unsigned*)&sth[ww][lane]);
            st = s_;
            thresh = umin(thresh, st);
            thrp = thr_from(thresh, qw);

            #pragma unroll 8
            for (int t = t0; t < t0 + 64; ++t) {
                float4 c = tile[w][t];
                // key = |c|^2+eps - 2 q.c   (dist - qw, ordering-equivalent)
                float key = fmaf(c.x, qx, fmaf(c.y, qy, fmaf(c.z, qz, c.w)));
                bool hit = key < thrp;      // conservative superset of pk<thresh
                if (__any_sync(0xffffffffu, hit && pval)) {
                    if (pval) {             // pack + exact IMNMX insert (rare path)
                        unsigned ck = (__float_as_uint(pkey + qw) & ~IDXMASK) | pidx;
                        #pragma unroll
                        for (int s = 0; s < KNN; ++s) {
                            unsigned lo = umin(ck, a[s]);
                            ck = umax(ck, a[s]);
                            a[s] = lo;
                        }
                        thresh = umin(a[KNN-1], st);
                        thrp = thr_from(thresh, qw);
                    }
                    sth[w][lane] = a[KNN-1];
                    pval = false;
                }
                if (hit) { pkey = key; pidx = (unsigned)(c0 + t); pval = true; }
            }
        }
    }
    if (pval) {                                  // final flush
        unsigned ck = (__float_as_uint(pkey + qw) & ~IDXMASK) | pidx;
        #pragma unroll
        for (int s = 0; s < KNN; ++s) {
            unsigned lo = umin(ck, a[s]); ck = umax(ck, a[s]); a[s] = lo;
        }
    }

    // ---- 8-way merge of sorted 16-lists ----
    #pragma unroll
    for (int s = 0; s < KNN; ++s) mm[s*(SPLIT*32) + w*32 + lane] = a[s];
    __syncthreads();
    if (w == 0) {
        int p0=0,p1=0,p2=0,p3=0,p4=0,p5=0,p6=0,p7=0;
        int* op = g_idx + (size_t)qg*KNN;
        #pragma unroll
        for (int s = 0; s < KNN; ++s) {
            unsigned h0 = mm[p0*256 +   0 + lane];
            unsigned h1 = mm[p1*256 +  32 + lane];
            unsigned h2 = mm[p2*256 +  64 + lane];
            unsigned h3 = mm[p3*256 +  96 + lane];
            unsigned h4 = mm[p4*256 + 128 + lane];
            unsigned h5 = mm[p5*256 + 160 + lane];
            unsigned h6 = mm[p6*256 + 192 + lane];
            unsigned h7 = mm[p7*256 + 224 + lane];
            unsigned best = h0; int bw = 0;
            if (h1 < best) { best = h1; bw = 1; }
            if (h2 < best) { best = h2; bw = 2; }
            if (h3 < best) { best = h3; bw = 3; }
            if (h4 < best) { best = h4; bw = 4; }
            if (h5 < best) { best = h5; bw = 5; }
            if (h6 < best) { best = h6; bw = 6; }
            if (h7 < best) { best = h7; bw = 7; }
            op[s] = (int)(best & IDXMASK) + bw*CHUNK;
            p0 += (bw==0); p1 += (bw==1); p2 += (bw==2); p3 += (bw==3);
            p4 += (bw==4); p5 += (bw==5); p6 += (bw==6); p7 += (bw==7);
        }
    }
}

// ---------------- v = feat @ Wv + bv ----------------
__global__ void k_gemm_v(const float* __restrict__ feat, const float* __restrict__ Wv,
                         const float* __restrict__ bv) {
    __shared__ float As[16][132];
    __shared__ float Ws[16][132];
    int m0 = blockIdx.x*128;
    int tx = threadIdx.x & 15, ty = threadIdx.x >> 4;
    float acc[8][8];
    #pragma unroll
    for (int i = 0; i < 8; ++i)
        #pragma unroll
        for (int j = 0; j < 8; ++j) acc[i][j] = 0.f;

    for (int kc = 0; kc < D; kc += 16) {
        __syncthreads();
        { // A chunk transposed into As[k][m]
            int c = threadIdx.x & 3, r = threadIdx.x >> 2;
            #pragma unroll
            for (int rr = 0; rr < 2; ++rr) {
                int mm = r + rr*64;
                float4 v = *(const float4*)&feat[(size_t)(m0+mm)*D + kc + c*4];
                As[c*4+0][mm] = v.x; As[c*4+1][mm] = v.y;
                As[c*4+2][mm] = v.z; As[c*4+3][mm] = v.w;
            }
        }
        { // W chunk
            int k = threadIdx.x >> 5, c4 = threadIdx.x & 31;
            #pragma unroll
            for (int kk = 0; kk < 2; ++kk) {
                float4 v = *(const float4*)&Wv[(size_t)(kc + k + kk*8)*D + c4*4];
                Ws[k + kk*8][c4*4+0] = v.x; Ws[k + kk*8][c4*4+1] = v.y;
                Ws[k + kk*8][c4*4+2] = v.z; Ws[k + kk*8][c4*4+3] = v.w;
            }
        }
        __syncthreads();
        #pragma unroll
        for (int k = 0; k < 16; ++k) {
            float a[8], bb[8];
            #pragma unroll
            for (int i = 0; i < 8; ++i) a[i]  = As[k][ty*8 + i];
            #pragma unroll
            for (int j = 0; j < 8; ++j) bb[j] = Ws[k][tx*8 + j];
            #pragma unroll
            for (int i = 0; i < 8; ++i)
                #pragma unroll
                for (int j = 0; j < 8; ++j) acc[i][j] = fmaf(a[i], bb[j], acc[i][j]);
        }
    }
    #pragma unroll
    for (int i = 0; i < 8; ++i) {
        int m = m0 + ty*8 + i;
        #pragma unroll
        for (int j = 0; j < 8; ++j) acc[i][j] += bv[tx*8 + j];
        *(float4*)&g_v[(size_t)m*D + tx*8]     = make_float4(acc[i][0], acc[i][1], acc[i][2], acc[i][3]);
        *(float4*)&g_v[(size_t)m*D + tx*8 + 4] = make_float4(acc[i][4], acc[i][5], acc[i][6], acc[i][7]);
    }
}

// ---------------- fused attention (warp per point) ----------------
__global__ void k_fuse(const float* __restrict__ xyz, const float* __restrict__ Wp1,
                       const float* __restrict__ bp1) {
    __shared__ float sw0[D], sw1[D], sw2[D], sb1[D], srs[D];
    int tid = threadIdx.x;
    sw0[tid] = Wp1[tid]; sw1[tid] = Wp1[D + tid]; sw2[tid] = Wp1[2*D + tid];
    sb1[tid] = bp1[tid]; srs[tid] = g_wp2rs[tid];
    __syncthreads();

    int warp = tid >> 5, lane = tid & 31;
    int p = blockIdx.x*4 + warp;
    int bbase = p & ~(NPTS-1);   // b*NPTS

    float w0[4], w1[4], w2[4], b1r[4], rs[4];
    #pragma unroll
    for (int i = 0; i < 4; ++i) {
        int d = lane + 32*i;
        w0[i] = sw0[d]; w1[i] = sw1[d]; w2[i] = sw2[d]; b1r[i] = sb1[d]; rs[i] = srs[d];
    }

    float rx = 0.f, ry = 0.f, rz = 0.f, ks = 0.f; int row = 0;
    if (lane < KNN) {
        int nb = g_idx[(size_t)p*KNN + lane];
        row = bbase + nb;
        float qx = xyz[3*p], qy = xyz[3*p+1], qz = xyz[3*p+2];
        rx = qx - xyz[3*row]; ry = qy - xyz[3*row+1]; rz = qz - xyz[3*row+2];
        ks = g_ksum[row];
    }

    // pass 1: attention logits  score_k = h_k . rowsum(Wp2) - ksum_k
    float mysc = -CUDART_INF_F;
    #pragma unroll
    for (int k = 0; k < KNN; ++k) {
        float bx = __shfl_sync(0xffffffffu, rx, k);
        float by = __shfl_sync(0xffffffffu, ry, k);
        float bz = __shfl_sync(0xffffffffu, rz, k);
        float part = 0.f;
        #pragma unroll
        for (int i = 0; i < 4; ++i) {
            float h = fmaf(bx, w0[i], fmaf(by, w1[i], fmaf(bz, w2[i], b1r[i])));
            h = fmaxf(h, 0.f);
            part = fmaf(h, rs[i], part);
        }
        #pragma unroll
        for (int off = 16; off; off >>= 1) part += __shfl_xor_sync(0xffffffffu, part, off);
        if (lane == k) mysc = part - ks;
    }
    // softmax over the 16 neighbor lanes
    float mx = mysc;
    #pragma unroll
    for (int off = 16; off; off >>= 1) mx = fmaxf(mx, __shfl_xor_sync(0xffffffffu, mx, off));
    float e = (lane < KNN) ? __expf(mysc - mx) : 0.f;
    float ssum = e;
    #pragma unroll
    for (int off = 16; off; off >>= 1) ssum += __shfl_xor_sync(0xffffffffu, ssum, off);
    float attn = e / ssum;

    // pass 2: hbar = sum attn*h, vbar = sum attn*v
    float hb[4] = {0,0,0,0}, vb[4] = {0,0,0,0};
    #pragma unroll
    for (int k = 0; k < KNN; ++k) {
        float a  = __shfl_sync(0xffffffffu, attn, k);
        float bx = __shfl_sync(0xffffffffu, rx, k);
        float by = __shfl_sync(0xffffffffu, ry, k);
        float bz = __shfl_sync(0xffffffffu, rz, k);
        int   r  = __shfl_sync(0xffffffffu, row, k);
        const float* vr = g_v + (size_t)r*D;
        #pragma unroll
        for (int i = 0; i < 4; ++i) {
            int d = lane + 32*i;
            float h = fmaf(bx, w0[i], fmaf(by, w1[i], fmaf(bz, w2[i], b1r[i])));
            h = fmaxf(h, 0.f);
            hb[i] = fmaf(a, h, hb[i]);
            vb[i] = fmaf(a, vr[d], vb[i]);
        }
    }
    #pragma unroll
    for (int i = 0; i < 4; ++i) {
        int d = lane + 32*i;
        g_hbar[(size_t)p*D + d] = hb[i];
        g_vbar[(size_t)p*D + d] = vb[i];
    }
}

// ---------------- out = feat + gamma*(vbar@Wo + hbar@Wf + cvec) ----------------
__global__ void k_out(const float* __restrict__ feat, const float* __restrict__ Wo,
                      const float* __restrict__ gamma, float* __restrict__ out) {
    __shared__ float As[16][132];
    __shared__ float Ws[16][132];
    int m0 = blockIdx.x*128;
    int tx = threadIdx.x & 15, ty = threadIdx.x >> 4;
    float acc[8][8];
    #pragma unroll
    for (int i = 0; i < 8; ++i)
        #pragma unroll
        for (int j = 0; j < 8; ++j) acc[i][j] = 0.f;

    for (int ph = 0; ph < 2; ++ph) {
        const float* A = ph ? g_hbar : g_vbar;
        const float* W = ph ? g_wf   : Wo;
        for (int kc = 0; kc < D; kc += 16) {
            __syncthreads();
            { int c = threadIdx.x & 3, r = threadIdx.x >> 2;
              #pragma unroll
              for (int rr = 0; rr < 2; ++rr) {
                  int mm = r + rr*64;
                  float4 v = *(const float4*)&A[(size_t)(m0+mm)*D + kc + c*4];
                  As[c*4+0][mm] = v.x; As[c*4+1][mm] = v.y;
                  As[c*4+2][mm] = v.z; As[c*4+3][mm] = v.w;
              }
            }
            { int k = threadIdx.x >> 5, c4 = threadIdx.x & 31;
              #pragma unroll
              for (int kk = 0; kk < 2; ++kk) {
                  float4 v = *(const float4*)&W[(size_t)(kc + k + kk*8)*D + c4*4];
                  Ws[k + kk*8][c4*4+0] = v.x; Ws[k + kk*8][c4*4+1] = v.y;
                  Ws[k + kk*8][c4*4+2] = v.z; Ws[k + kk*8][c4*4+3] = v.w;
              }
            }
            __syncthreads();
            #pragma unroll
            for (int k = 0; k < 16; ++k) {
                float a[8], bb[8];
                #pragma unroll
                for (int i = 0; i < 8; ++i) a[i]  = As[k][ty*8 + i];
                #pragma unroll
                for (int j = 0; j < 8; ++j) bb[j] = Ws[k][tx*8 + j];
                #pragma unroll
                for (int i = 0; i < 8; ++i)
                    #pragma unroll
                    for (int j = 0; j < 8; ++j) acc[i][j] = fmaf(a[i], bb[j], acc[i][j]);
            }
        }
    }
    float g = *gamma;
    float cv[8];
    #pragma unroll
    for (int j = 0; j < 8; ++j) cv[j] = g_cvec[tx*8 + j];
    #pragma unroll
    for (int i = 0; i < 8; ++i) {
        int m = m0 + ty*8 + i;
        float4 f0 = *(const float4*)&feat[(size_t)m*D + tx*8];
        float4 f1 = *(const float4*)&feat[(size_t)m*D + tx*8 + 4];
        float o0 = f0.x + g*(acc[i][0] + cv[0]);
        float o1 = f0.y + g*(acc[i][1] + cv[1]);
        float o2 = f0.z + g*(acc[i][2] + cv[2]);
        float o3 = f0.w + g*(acc[i][3] + cv[3]);
        float o4 = f1.x + g*(acc[i][4] + cv[4]);
        float o5 = f1.y + g*(acc[i][5] + cv[5]);
        float o6 = f1.z + g*(acc[i][6] + cv[6]);
        float o7 = f1.w + g*(acc[i][7] + cv[7]);
        *(float4*)&out[(size_t)m*D + tx*8]     = make_float4(o0, o1, o2, o3);
        *(float4*)&out[(size_t)m*D + tx*8 + 4] = make_float4(o4, o5, o6, o7);
    }
}

// ---------------- launch ----------------
extern "C" void kernel_launch(void* const* d_in, const int* in_sizes, int n_in,
                              void* d_out, int out_size) {
    const float* xyz  = (const float*)d_in[0];
    const float* feat = (const float*)d_in[1];
    // d_in[2]=Wq, d_in[3]=bq, d_in[5]=bk : mathematically cancel in softmax, unused
    const float* Wk   = (const float*)d_in[4];
    const float* Wv   = (const float*)d_in[6];
    const float* bv   = (const float*)d_in[7];
    const float* Wp1  = (const float*)d_in[8];
    const float* bp1  = (const float*)d_in[9];
    const float* Wp2  = (const float*)d_in[10];
    const float* bp2  = (const float*)d_in[11];
    const float* Wo   = (const float*)d_in[12];
    const float* bo   = (const float*)d_in[13];
    const float* gmm  = (const float*)d_in[14];
    float* out = (float*)d_out;

    k_weights<<<1, 128>>>(Wk, Wp2, bp2, Wo, bo);
    k_wfused<<<64, 256>>>(Wp2, Wo);
    k_prep<<<BN/8, 256>>>(xyz, feat);
    k_topk<<<dim3(NPTS/32, NB), 256>>>(xyz);
    k_gemm_v<<<BN/128, 256>>>(feat, Wv, bv);
    k_fuse<<<BN/4, 128>>>(xyz, Wp1, bp1);
    k_out<<<BN/128, 256>>>(feat, Wo, gmm, out);
}